// round 1
// baseline (speedup 1.0000x reference)
#include <cuda_runtime.h>
#include <cuda_bf16.h>
#include <cstdint>

// ---------------------------------------------------------------------------
// CMA block: pool2x2 -> QKV 1x1 conv -> softmax attention (N=4096, d=64) ->
// O 1x1 conv + BN (folded, done at low res) -> bilinear 2x -> lrelu -> +rgb
// ---------------------------------------------------------------------------

#define BB 8
#define NTOK 4096   // 64*64 tokens per batch
#define DD 64
// scale * log2(e) folded into Q so softmax numerator = exp2(q'.k)
#define QSCALE 0.18033688011112042f

// scratch (device globals: no allocation allowed)
__device__ __align__(16) __nv_bfloat16 g_Q[BB * NTOK * DD];  // [b][n][c]
__device__ __align__(16) __nv_bfloat16 g_K[BB * NTOK * DD];  // [b][n][c]
__device__ __align__(16) __nv_bfloat16 g_V[BB * DD * NTOK];  // [b][c][n]
__device__ __align__(16) float g_Z[BB * NTOK * DD];          // attn out [b][n][c]
__device__ __align__(16) float g_Y[BB * DD * NTOK];          // o-proj   [b][c][n]

__device__ __forceinline__ float ex2f(float x) {
    float r; asm("ex2.approx.f32 %0, %1;" : "=f"(r) : "f"(x)); return r;
}
__device__ __forceinline__ unsigned packbf(float lo, float hi) {
    unsigned r; asm("cvt.rn.bf16x2.f32 %0, %1, %2;" : "=r"(r) : "f"(hi), "f"(lo)); return r;
}
__device__ __forceinline__ void mma_bf16(float (&d)[4], const unsigned (&a)[4],
                                         unsigned b0, unsigned b1) {
    asm volatile(
        "mma.sync.aligned.m16n8k16.row.col.f32.bf16.bf16.f32 "
        "{%0,%1,%2,%3}, {%4,%5,%6,%7}, {%8,%9}, {%0,%1,%2,%3};\n"
        : "+f"(d[0]), "+f"(d[1]), "+f"(d[2]), "+f"(d[3])
        : "r"(a[0]), "r"(a[1]), "r"(a[2]), "r"(a[3]), "r"(b0), "r"(b1));
}

// ---------------------------------------------------------------------------
// Stage 1: pool 2x2 + QKV projection.
// grid (64 ds-rows, B, 3 modes): mode 0: Q from rgb; 1: K from freq; 2: V from freq
// ---------------------------------------------------------------------------
__global__ __launch_bounds__(128) void qkv_kernel(
    const float* __restrict__ rgb, const float* __restrict__ freq,
    const float* __restrict__ w_q, const float* __restrict__ b_q,
    const float* __restrict__ w_k, const float* __restrict__ b_k,
    const float* __restrict__ w_v, const float* __restrict__ b_v) {
    int y = blockIdx.x, b = blockIdx.y, mode = blockIdx.z;
    const float* src  = (mode == 0) ? rgb : freq;
    const float* w    = (mode == 0) ? w_q : (mode == 1 ? w_k : w_v);
    const float* bias = (mode == 0) ? b_q : (mode == 1 ? b_k : b_v);

    __shared__ float xs[64][64];   // pooled input [c][t]
    __shared__ float Ws[64][65];   // weights transposed [c][o]
    int tid = threadIdx.x;

    const float* base = src + (((size_t)b * 64) * 128 + 2 * y) * 128;
    for (int idx = tid; idx < 4096; idx += 128) {
        int c = idx >> 6, t = idx & 63;
        const float* p = base + (size_t)c * 128 * 128 + 2 * t;
        float2 a0 = *(const float2*)p;
        float2 a1 = *(const float2*)(p + 128);
        xs[c][t] = 0.25f * (a0.x + a0.y + a1.x + a1.y);
    }
    for (int idx = tid; idx < 4096; idx += 128) {
        int o = idx >> 6, c = idx & 63;
        Ws[c][o] = w[idx];
    }
    __syncthreads();

    int og = tid >> 3, tg = tid & 7;   // 4 out-channels x 8 tokens per thread
    int o0 = og * 4;
    float acc[4][8];
    #pragma unroll
    for (int oi = 0; oi < 4; oi++) {
        float bv = bias[o0 + oi];
        #pragma unroll
        for (int ti = 0; ti < 8; ti++) acc[oi][ti] = bv;
    }
    for (int c = 0; c < 64; c++) {
        float wv[4], xv[8];
        #pragma unroll
        for (int oi = 0; oi < 4; oi++) wv[oi] = Ws[c][o0 + oi];
        #pragma unroll
        for (int ti = 0; ti < 8; ti++) xv[ti] = xs[c][ti * 8 + tg];
        #pragma unroll
        for (int oi = 0; oi < 4; oi++)
            #pragma unroll
            for (int ti = 0; ti < 8; ti++) acc[oi][ti] += wv[oi] * xv[ti];
    }

    if (mode == 2) {  // V: [b][c][n], coalesced over tokens
        #pragma unroll
        for (int oi = 0; oi < 4; oi++)
            #pragma unroll
            for (int ti = 0; ti < 8; ti++) {
                int t = ti * 8 + tg;
                g_V[((size_t)b * 64 + o0 + oi) * NTOK + y * 64 + t] =
                    __float2bfloat16(acc[oi][ti]);
            }
    } else {          // Q/K: [b][n][c]
        __nv_bfloat16* dst = (mode == 0) ? g_Q : g_K;
        float s = (mode == 0) ? QSCALE : 1.0f;
        #pragma unroll
        for (int ti = 0; ti < 8; ti++) {
            int t = ti * 8 + tg;
            size_t rowoff = ((size_t)b * NTOK + y * 64 + t) * 64 + o0;
            #pragma unroll
            for (int oi = 0; oi < 4; oi += 2) {
                unsigned pr = packbf(acc[oi][ti] * s, acc[oi + 1][ti] * s);
                *(unsigned*)&dst[rowoff + oi] = pr;
            }
        }
    }
}

// ---------------------------------------------------------------------------
// Stage 2: fused attention (no max-subtraction needed: logits are tiny,
// p = exp2(q'.k), z = sum(p*V)/sum(p)). BM=128 queries per CTA, BN=64 keys/iter.
// 8 warps, each warp owns 16 query rows. bf16 mma.sync m16n8k16, fp32 accum.
// ---------------------------------------------------------------------------
__global__ __launch_bounds__(256, 2) void attn_kernel() {
    int b = blockIdx.y;
    int qbase = blockIdx.x * 128;
    __shared__ __align__(16) __nv_bfloat16 Qs[128][72];
    __shared__ __align__(16) __nv_bfloat16 Ks[64][72];
    __shared__ __align__(16) __nv_bfloat16 VTs[64][72];   // [chan][key]

    int tid = threadIdx.x, lane = tid & 31, warp = tid >> 5;
    int grp = lane >> 2, tig = lane & 3;

    {   // load Q tile [128][64]
        const __nv_bfloat16* Qp = g_Q + ((size_t)b * NTOK + qbase) * 64;
        for (int i = tid; i < 1024; i += 256) {
            int r = i >> 3, sg = i & 7;
            *(uint4*)&Qs[r][sg * 8] = *(const uint4*)(Qp + r * 64 + sg * 8);
        }
    }
    __syncthreads();

    unsigned qa[4][4];
    int wr = warp * 16;
    #pragma unroll
    for (int ks = 0; ks < 4; ks++) {
        int c0 = ks * 16 + tig * 2;
        qa[ks][0] = *(const unsigned*)&Qs[wr + grp][c0];
        qa[ks][1] = *(const unsigned*)&Qs[wr + grp + 8][c0];
        qa[ks][2] = *(const unsigned*)&Qs[wr + grp][c0 + 8];
        qa[ks][3] = *(const unsigned*)&Qs[wr + grp + 8][c0 + 8];
    }

    float oacc[8][4];
    #pragma unroll
    for (int dt = 0; dt < 8; dt++)
        #pragma unroll
        for (int k = 0; k < 4; k++) oacc[dt][k] = 0.f;
    float den0 = 0.f, den1 = 0.f;

    const __nv_bfloat16* Kp = g_K + (size_t)b * NTOK * 64;
    const __nv_bfloat16* Vp = g_V + (size_t)b * 64 * NTOK;

    for (int kt = 0; kt < 64; kt++) {
        __syncthreads();
        for (int i = tid; i < 512; i += 256) {
            int r = i >> 3, sg = i & 7;
            *(uint4*)&Ks[r][sg * 8]  = *(const uint4*)(Kp + (kt * 64 + r) * 64 + sg * 8);
            *(uint4*)&VTs[r][sg * 8] = *(const uint4*)(Vp + (size_t)r * NTOK + kt * 64 + sg * 8);
        }
        __syncthreads();

        unsigned pa[4][4];
        // compute S in 2 halves of 4 n-tiles to bound live registers
        #pragma unroll
        for (int half = 0; half < 2; half++) {
            float s[4][4];
            #pragma unroll
            for (int nt = 0; nt < 4; nt++) {
                #pragma unroll
                for (int k = 0; k < 4; k++) s[nt][k] = 0.f;
                int krow = (half * 4 + nt) * 8 + grp;
                #pragma unroll
                for (int ks = 0; ks < 4; ks++) {
                    int c0 = ks * 16 + tig * 2;
                    unsigned kb0 = *(const unsigned*)&Ks[krow][c0];
                    unsigned kb1 = *(const unsigned*)&Ks[krow][c0 + 8];
                    mma_bf16(s[nt], qa[ks], kb0, kb1);
                }
            }
            #pragma unroll
            for (int j = 0; j < 2; j++) {
                float p0 = ex2f(s[2 * j][0]),     p1 = ex2f(s[2 * j][1]);
                float p2 = ex2f(s[2 * j][2]),     p3 = ex2f(s[2 * j][3]);
                float p4 = ex2f(s[2 * j + 1][0]), p5 = ex2f(s[2 * j + 1][1]);
                float p6 = ex2f(s[2 * j + 1][2]), p7 = ex2f(s[2 * j + 1][3]);
                den0 += p0 + p1 + p4 + p5;
                den1 += p2 + p3 + p6 + p7;
                pa[half * 2 + j][0] = packbf(p0, p1);
                pa[half * 2 + j][1] = packbf(p2, p3);
                pa[half * 2 + j][2] = packbf(p4, p5);
                pa[half * 2 + j][3] = packbf(p6, p7);
            }
        }
        // O += P @ V  (k = keys, n = head dim)
        #pragma unroll
        for (int dt = 0; dt < 8; dt++) {
            int vrow = dt * 8 + grp;
            #pragma unroll
            for (int j = 0; j < 4; j++) {
                int c0 = j * 16 + tig * 2;
                unsigned vb0 = *(const unsigned*)&VTs[vrow][c0];
                unsigned vb1 = *(const unsigned*)&VTs[vrow][c0 + 8];
                mma_bf16(oacc[dt], pa[j], vb0, vb1);
            }
        }
    }

    den0 += __shfl_xor_sync(0xffffffffu, den0, 1);
    den0 += __shfl_xor_sync(0xffffffffu, den0, 2);
    den1 += __shfl_xor_sync(0xffffffffu, den1, 1);
    den1 += __shfl_xor_sync(0xffffffffu, den1, 2);
    float i0 = 1.f / den0, i1 = 1.f / den1;

    int r0 = qbase + wr + grp, r1 = r0 + 8;
    #pragma unroll
    for (int dt = 0; dt < 8; dt++) {
        int c = dt * 8 + tig * 2;
        *(float2*)&g_Z[((size_t)b * NTOK + r0) * 64 + c] =
            make_float2(oacc[dt][0] * i0, oacc[dt][1] * i0);
        *(float2*)&g_Z[((size_t)b * NTOK + r1) * 64 + c] =
            make_float2(oacc[dt][2] * i1, oacc[dt][3] * i1);
    }
}

// ---------------------------------------------------------------------------
// Stage 3a: O-projection + folded BN at 64x64 resolution (conv1x1 & BN commute
// with bilinear). grid (64 ds-rows, B).
// ---------------------------------------------------------------------------
__global__ __launch_bounds__(128) void convo_kernel(
    const float* __restrict__ w_o, const float* __restrict__ b_o,
    const float* __restrict__ gamma, const float* __restrict__ beta,
    const float* __restrict__ mean, const float* __restrict__ var) {
    int y = blockIdx.x, b = blockIdx.y;
    __shared__ float zs[64][65];
    __shared__ float Wsm[64][65];
    __shared__ float invs[64], bsm[64];
    int tid = threadIdx.x;

    if (tid < 64) {
        float inv = gamma[tid] * rsqrtf(var[tid] + 1e-5f);
        invs[tid] = inv;
        bsm[tid] = (b_o[tid] - mean[tid]) * inv + beta[tid];
    }
    __syncthreads();
    for (int idx = tid; idx < 4096; idx += 128) {
        int o = idx >> 6, c = idx & 63;
        Wsm[c][o] = w_o[idx] * invs[o];
    }
    for (int idx = tid; idx < 4096; idx += 128) {
        int t = idx >> 6, c = idx & 63;
        zs[t][c] = g_Z[((size_t)b * NTOK + y * 64 + t) * 64 + c];
    }
    __syncthreads();

    int og = tid >> 3, tg = tid & 7;
    int o0 = og * 4;
    float acc[4][8];
    #pragma unroll
    for (int oi = 0; oi < 4; oi++) {
        float bv = bsm[o0 + oi];
        #pragma unroll
        for (int ti = 0; ti < 8; ti++) acc[oi][ti] = bv;
    }
    for (int c = 0; c < 64; c++) {
        float wv[4], xv[8];
        #pragma unroll
        for (int oi = 0; oi < 4; oi++) wv[oi] = Wsm[c][o0 + oi];
        #pragma unroll
        for (int ti = 0; ti < 8; ti++) xv[ti] = zs[ti * 8 + tg][c];
        #pragma unroll
        for (int oi = 0; oi < 4; oi++)
            #pragma unroll
            for (int ti = 0; ti < 8; ti++) acc[oi][ti] += wv[oi] * xv[ti];
    }
    #pragma unroll
    for (int oi = 0; oi < 4; oi++)
        #pragma unroll
        for (int ti = 0; ti < 8; ti++)
            g_Y[((size_t)b * 64 + o0 + oi) * NTOK + y * 64 + ti * 8 + tg] = acc[oi][ti];
}

// ---------------------------------------------------------------------------
// Stage 3b: bilinear 2x upsample (align_corners=False) + LeakyReLU + residual.
// grid (128 h, 64 c, 8 b), 128 threads = one output row.
// ---------------------------------------------------------------------------
__global__ __launch_bounds__(128) void final_kernel(
    const float* __restrict__ rgb, float* __restrict__ out) {
    int w = threadIdx.x, h = blockIdx.x, c = blockIdx.y, b = blockIdx.z;
    float ysf = fmaxf(h * 0.5f - 0.25f, 0.f);
    int y0 = (int)ysf; float wy = ysf - (float)y0; int y1 = min(y0 + 1, 63);
    float xsf = fmaxf(w * 0.5f - 0.25f, 0.f);
    int x0 = (int)xsf; float wx = xsf - (float)x0; int x1 = min(x0 + 1, 63);

    const float* Yb = g_Y + ((size_t)b * 64 + c) * NTOK;
    float v00 = Yb[y0 * 64 + x0], v01 = Yb[y0 * 64 + x1];
    float v10 = Yb[y1 * 64 + x0], v11 = Yb[y1 * 64 + x1];
    float r0 = v00 + wx * (v01 - v00);
    float r1 = v10 + wx * (v11 - v10);
    float v = r0 + wy * (r1 - r0);
    v = (v >= 0.f) ? v : 0.2f * v;

    size_t idx = (((size_t)b * 64 + c) * 128 + h) * 128 + w;
    out[idx] = rgb[idx] + v;
}

// ---------------------------------------------------------------------------
extern "C" void kernel_launch(void* const* d_in, const int* in_sizes, int n_in,
                              void* d_out, int out_size) {
    const float* rgb   = (const float*)d_in[0];
    const float* freq  = (const float*)d_in[1];
    const float* w_q   = (const float*)d_in[2];
    const float* b_q   = (const float*)d_in[3];
    const float* w_k   = (const float*)d_in[4];
    const float* b_k   = (const float*)d_in[5];
    const float* w_v   = (const float*)d_in[6];
    const float* b_v   = (const float*)d_in[7];
    const float* w_o   = (const float*)d_in[8];
    const float* b_o   = (const float*)d_in[9];
    const float* gamma = (const float*)d_in[10];
    const float* beta  = (const float*)d_in[11];
    const float* mean  = (const float*)d_in[12];
    const float* var   = (const float*)d_in[13];
    float* out = (float*)d_out;

    qkv_kernel<<<dim3(64, 8, 3), 128>>>(rgb, freq, w_q, b_q, w_k, b_k, w_v, b_v);
    attn_kernel<<<dim3(32, 8), 256>>>();
    convo_kernel<<<dim3(64, 8), 128>>>(w_o, b_o, gamma, beta, mean, var);
    final_kernel<<<dim3(128, 64, 8), 128>>>(rgb, out);
}

// round 4
// speedup vs baseline: 1.1885x; 1.1885x over previous
#include <cuda_runtime.h>
#include <cuda_bf16.h>
#include <cstdint>

// ---------------------------------------------------------------------------
// CMA block: pool2x2 -> QKV 1x1 conv -> softmax attention (N=4096, d=64) ->
// O 1x1 conv + BN (folded, done at low res) -> bilinear 2x -> lrelu -> +rgb
// ---------------------------------------------------------------------------

#define BB 8
#define NTOK 4096   // 64*64 tokens per batch
#define DD 64
// scale * log2(e) folded into Q so softmax numerator = exp2(q'.k)
#define QSCALE 0.18033688011112042f

// scratch (device globals: no allocation allowed)
__device__ __align__(16) __nv_bfloat16 g_Q[BB * NTOK * DD];  // [b][n][c]
__device__ __align__(16) __nv_bfloat16 g_K[BB * NTOK * DD];  // [b][n][c]
__device__ __align__(16) __nv_bfloat16 g_V[BB * DD * NTOK];  // [b][c][n]
__device__ __align__(16) float g_Z[BB * NTOK * DD];          // attn out [b][n][c]
__device__ __align__(16) float g_Y[BB * DD * NTOK];          // o-proj   [b][c][n]

__device__ __forceinline__ float ex2f(float x) {
    float r; asm("ex2.approx.f32 %0, %1;" : "=f"(r) : "f"(x)); return r;
}
__device__ __forceinline__ unsigned packbf(float lo, float hi) {
    unsigned r; asm("cvt.rn.bf16x2.f32 %0, %1, %2;" : "=r"(r) : "f"(hi), "f"(lo)); return r;
}
__device__ __forceinline__ void mma_bf16(float (&d)[4], const unsigned (&a)[4],
                                         unsigned b0, unsigned b1) {
    asm volatile(
        "mma.sync.aligned.m16n8k16.row.col.f32.bf16.bf16.f32 "
        "{%0,%1,%2,%3}, {%4,%5,%6,%7}, {%8,%9}, {%0,%1,%2,%3};\n"
        : "+f"(d[0]), "+f"(d[1]), "+f"(d[2]), "+f"(d[3])
        : "r"(a[0]), "r"(a[1]), "r"(a[2]), "r"(a[3]), "r"(b0), "r"(b1));
}
__device__ __forceinline__ void ldsm4(unsigned& r0, unsigned& r1, unsigned& r2,
                                      unsigned& r3, uint32_t addr) {
    asm volatile("ldmatrix.sync.aligned.m8n8.x4.shared.b16 {%0,%1,%2,%3}, [%4];"
                 : "=r"(r0), "=r"(r1), "=r"(r2), "=r"(r3) : "r"(addr));
}
__device__ __forceinline__ void cp16(uint32_t s, const void* g) {
    asm volatile("cp.async.cg.shared.global [%0], [%1], 16;" :: "r"(s), "l"(g));
}

// ---------------------------------------------------------------------------
// Stage 1: pool 2x2 + QKV projection. grid (64 ds-rows, B, 2 modes).
// mode 0: Q from rgb; mode 1: K then V from freq (freq read ONCE).
// ---------------------------------------------------------------------------
__device__ __forceinline__ void proj_compute(
    const float (*xs)[64], const float (*Ws)[65], const float* bias,
    int tid, float (&acc)[4][8]) {
    int og = tid >> 3, tg = tid & 7;
    int o0 = og * 4;
    #pragma unroll
    for (int oi = 0; oi < 4; oi++) {
        float bv = bias[o0 + oi];
        #pragma unroll
        for (int ti = 0; ti < 8; ti++) acc[oi][ti] = bv;
    }
    for (int c = 0; c < 64; c++) {
        float wv[4], xv[8];
        #pragma unroll
        for (int oi = 0; oi < 4; oi++) wv[oi] = Ws[c][o0 + oi];
        #pragma unroll
        for (int ti = 0; ti < 8; ti++) xv[ti] = xs[c][ti * 8 + tg];
        #pragma unroll
        for (int oi = 0; oi < 4; oi++)
            #pragma unroll
            for (int ti = 0; ti < 8; ti++) acc[oi][ti] += wv[oi] * xv[ti];
    }
}

__global__ __launch_bounds__(128) void qkv_kernel(
    const float* __restrict__ rgb, const float* __restrict__ freq,
    const float* __restrict__ w_q, const float* __restrict__ b_q,
    const float* __restrict__ w_k, const float* __restrict__ b_k,
    const float* __restrict__ w_v, const float* __restrict__ b_v) {
    int y = blockIdx.x, b = blockIdx.y, mode = blockIdx.z;
    __shared__ float xs[64][64];   // pooled input [c][t]
    __shared__ float Ws[64][65];   // weights transposed [c][o]
    int tid = threadIdx.x;
    int og = tid >> 3, tg = tid & 7, o0 = (tid >> 3) * 4;
    (void)og;

    const float* src = (mode == 0) ? rgb : freq;
    const float* base = src + (((size_t)b * 64) * 128 + 2 * y) * 128;
    for (int idx = tid; idx < 4096; idx += 128) {
        int c = idx >> 6, t = idx & 63;
        const float* p = base + (size_t)c * 128 * 128 + 2 * t;
        float2 a0 = *(const float2*)p;
        float2 a1 = *(const float2*)(p + 128);
        xs[c][t] = 0.25f * (a0.x + a0.y + a1.x + a1.y);
    }

    const float* w0 = (mode == 0) ? w_q : w_k;
    for (int idx = tid; idx < 4096; idx += 128) {
        int o = idx >> 6, c = idx & 63;
        Ws[c][o] = w0[idx];
    }
    __syncthreads();

    float acc[4][8];
    proj_compute(xs, Ws, (mode == 0) ? b_q : b_k, tid, acc);

    if (mode == 0) {   // Q: [b][n][c], pre-scaled
        #pragma unroll
        for (int ti = 0; ti < 8; ti++) {
            int t = ti * 8 + tg;
            size_t rowoff = ((size_t)b * NTOK + y * 64 + t) * 64 + o0;
            #pragma unroll
            for (int oi = 0; oi < 4; oi += 2)
                *(unsigned*)&g_Q[rowoff + oi] =
                    packbf(acc[oi][ti] * QSCALE, acc[oi + 1][ti] * QSCALE);
        }
        return;
    }
    // K: [b][n][c]
    #pragma unroll
    for (int ti = 0; ti < 8; ti++) {
        int t = ti * 8 + tg;
        size_t rowoff = ((size_t)b * NTOK + y * 64 + t) * 64 + o0;
        #pragma unroll
        for (int oi = 0; oi < 4; oi += 2)
            *(unsigned*)&g_K[rowoff + oi] = packbf(acc[oi][ti], acc[oi + 1][ti]);
    }
    __syncthreads();   // all Ws reads done before reload
    for (int idx = tid; idx < 4096; idx += 128) {
        int o = idx >> 6, c = idx & 63;
        Ws[c][o] = w_v[idx];
    }
    __syncthreads();
    proj_compute(xs, Ws, b_v, tid, acc);
    // V: [b][c][n]
    #pragma unroll
    for (int oi = 0; oi < 4; oi++)
        #pragma unroll
        for (int ti = 0; ti < 8; ti++) {
            int t = ti * 8 + tg;
            g_V[((size_t)b * 64 + o0 + oi) * NTOK + y * 64 + t] =
                __float2bfloat16(acc[oi][ti]);
        }
}

// ---------------------------------------------------------------------------
// Stage 2: fused attention. BM=128 queries per CTA, BN=64 keys/iter, 8 warps.
// No max-subtraction (logits tiny): p = exp2(q'.k), z = sum(p*V)/sum(p).
// ldmatrix operand loads, cp.async 2-stage double buffer, 1 barrier/iter.
// ---------------------------------------------------------------------------
__global__ __launch_bounds__(256, 2) void attn_kernel() {
    int b = blockIdx.y;
    int qbase = blockIdx.x * 128;
    // [stage][K/V][row][72]: row stride 144B (conflict-free for ldmatrix)
    __shared__ __align__(16) __nv_bfloat16 KVs[2][2][64][72];

    int tid = threadIdx.x, lane = tid & 31, warp = tid >> 5;
    int grp = lane >> 2, tig = lane & 3;

    const __nv_bfloat16* Kp = g_K + (size_t)b * NTOK * 64;
    const __nv_bfloat16* Vp = g_V + (size_t)b * 64 * NTOK;

    // A-fragments for Q loaded directly from gmem (once)
    unsigned qa[4][4];
    {
        const __nv_bfloat16* Qp = g_Q + ((size_t)b * NTOK + qbase + warp * 16 + grp) * 64;
        #pragma unroll
        for (int ks = 0; ks < 4; ks++) {
            qa[ks][0] = *(const unsigned*)(Qp + ks * 16 + tig * 2);
            qa[ks][1] = *(const unsigned*)(Qp + 8 * 64 + ks * 16 + tig * 2);
            qa[ks][2] = *(const unsigned*)(Qp + ks * 16 + 8 + tig * 2);
            qa[ks][3] = *(const unsigned*)(Qp + 8 * 64 + ks * 16 + 8 + tig * 2);
        }
    }

    uint32_t sb = (uint32_t)__cvta_generic_to_shared(&KVs[0][0][0][0]);
    const int STG = 2 * 64 * 144;   // stage stride bytes
    const int KVD = 64 * 144;       // K->V stride bytes
    // per-lane ldmatrix offset: tile = lane>>3, row-in-tile = lane&7
    uint32_t lmoff = (uint32_t)((lane & 7) * 144 + (lane >> 3) * 16);

    // cp.async tile loader: 512 16B chunks per K tile (and per V tile)
    int r0i = tid, r1i = tid + 256;
    int row0 = r0i >> 3, ch0 = r0i & 7, row1 = r1i >> 3, ch1 = r1i & 7;

    auto issue = [&](int kt, int st) {
        uint32_t kd = sb + st * STG;
        uint32_t vd = kd + KVD;
        cp16(kd + row0 * 144 + ch0 * 16, Kp + (kt * 64 + row0) * 64 + ch0 * 8);
        cp16(kd + row1 * 144 + ch1 * 16, Kp + (kt * 64 + row1) * 64 + ch1 * 8);
        cp16(vd + row0 * 144 + ch0 * 16, Vp + (size_t)row0 * NTOK + kt * 64 + ch0 * 8);
        cp16(vd + row1 * 144 + ch1 * 16, Vp + (size_t)row1 * NTOK + kt * 64 + ch1 * 8);
        asm volatile("cp.async.commit_group;" ::: "memory");
    };

    float oacc[8][4];
    #pragma unroll
    for (int dt = 0; dt < 8; dt++)
        #pragma unroll
        for (int k = 0; k < 4; k++) oacc[dt][k] = 0.f;
    float den0 = 0.f, den1 = 0.f;

    issue(0, 0);

    for (int kt = 0; kt < 64; kt++) {
        int st = kt & 1;
        asm volatile("cp.async.wait_group 0;" ::: "memory");
        __syncthreads();
        if (kt + 1 < 64) issue(kt + 1, st ^ 1);

        uint32_t Kb = sb + st * STG + lmoff;
        uint32_t Vb = Kb + KVD;

        unsigned pa[4][4];
        #pragma unroll
        for (int j = 0; j < 4; j++) {
            float s0[4] = {0.f, 0.f, 0.f, 0.f}, s1[4] = {0.f, 0.f, 0.f, 0.f};
            unsigned kb0[8], kb1[8];
            ldsm4(kb0[0], kb0[1], kb0[2], kb0[3], Kb + (2 * j) * 1152);
            ldsm4(kb0[4], kb0[5], kb0[6], kb0[7], Kb + (2 * j) * 1152 + 64);
            ldsm4(kb1[0], kb1[1], kb1[2], kb1[3], Kb + (2 * j + 1) * 1152);
            ldsm4(kb1[4], kb1[5], kb1[6], kb1[7], Kb + (2 * j + 1) * 1152 + 64);
            #pragma unroll
            for (int ks = 0; ks < 4; ks++) {
                mma_bf16(s0, qa[ks], kb0[2 * ks], kb0[2 * ks + 1]);
                mma_bf16(s1, qa[ks], kb1[2 * ks], kb1[2 * ks + 1]);
            }
            float p0 = ex2f(s0[0]), p1 = ex2f(s0[1]);
            float p2 = ex2f(s0[2]), p3 = ex2f(s0[3]);
            float p4 = ex2f(s1[0]), p5 = ex2f(s1[1]);
            float p6 = ex2f(s1[2]), p7 = ex2f(s1[3]);
            den0 += p0 + p1 + p4 + p5;
            den1 += p2 + p3 + p6 + p7;
            pa[j][0] = packbf(p0, p1);
            pa[j][1] = packbf(p2, p3);
            pa[j][2] = packbf(p4, p5);
            pa[j][3] = packbf(p6, p7);
        }
        #pragma unroll
        for (int dt = 0; dt < 8; dt++) {
            unsigned vb[8];
            ldsm4(vb[0], vb[1], vb[2], vb[3], Vb + dt * 1152);
            ldsm4(vb[4], vb[5], vb[6], vb[7], Vb + dt * 1152 + 64);
            #pragma unroll
            for (int j = 0; j < 4; j++)
                mma_bf16(oacc[dt], pa[j], vb[2 * j], vb[2 * j + 1]);
        }
    }

    den0 += __shfl_xor_sync(0xffffffffu, den0, 1);
    den0 += __shfl_xor_sync(0xffffffffu, den0, 2);
    den1 += __shfl_xor_sync(0xffffffffu, den1, 1);
    den1 += __shfl_xor_sync(0xffffffffu, den1, 2);
    float i0 = 1.f / den0, i1 = 1.f / den1;

    int r0 = qbase + warp * 16 + grp, r1 = r0 + 8;
    #pragma unroll
    for (int dt = 0; dt < 8; dt++) {
        int c = dt * 8 + tig * 2;
        *(float2*)&g_Z[((size_t)b * NTOK + r0) * 64 + c] =
            make_float2(oacc[dt][0] * i0, oacc[dt][1] * i0);
        *(float2*)&g_Z[((size_t)b * NTOK + r1) * 64 + c] =
            make_float2(oacc[dt][2] * i1, oacc[dt][3] * i1);
    }
}

// ---------------------------------------------------------------------------
// Stage 3a: O-projection + folded BN at 64x64 resolution. grid (64 ds-rows, B).
// ---------------------------------------------------------------------------
__global__ __launch_bounds__(128) void convo_kernel(
    const float* __restrict__ w_o, const float* __restrict__ b_o,
    const float* __restrict__ gamma, const float* __restrict__ beta,
    const float* __restrict__ mean, const float* __restrict__ var) {
    int y = blockIdx.x, b = blockIdx.y;
    __shared__ float zs[64][65];
    __shared__ float Wsm[64][65];
    __shared__ float invs[64], bsm[64];
    int tid = threadIdx.x;

    if (tid < 64) {
        float inv = gamma[tid] * rsqrtf(var[tid] + 1e-5f);
        invs[tid] = inv;
        bsm[tid] = (b_o[tid] - mean[tid]) * inv + beta[tid];
    }
    __syncthreads();
    for (int idx = tid; idx < 4096; idx += 128) {
        int o = idx >> 6, c = idx & 63;
        Wsm[c][o] = w_o[idx] * invs[o];
    }
    for (int idx = tid; idx < 4096; idx += 128) {
        int t = idx >> 6, c = idx & 63;
        zs[t][c] = g_Z[((size_t)b * NTOK + y * 64 + t) * 64 + c];
    }
    __syncthreads();

    int og = tid >> 3, tg = tid & 7;
    int o0 = og * 4;
    float acc[4][8];
    #pragma unroll
    for (int oi = 0; oi < 4; oi++) {
        float bv = bsm[o0 + oi];
        #pragma unroll
        for (int ti = 0; ti < 8; ti++) acc[oi][ti] = bv;
    }
    for (int c = 0; c < 64; c++) {
        float wv[4], xv[8];
        #pragma unroll
        for (int oi = 0; oi < 4; oi++) wv[oi] = Wsm[c][o0 + oi];
        #pragma unroll
        for (int ti = 0; ti < 8; ti++) xv[ti] = zs[ti * 8 + tg][c];
        #pragma unroll
        for (int oi = 0; oi < 4; oi++)
            #pragma unroll
            for (int ti = 0; ti < 8; ti++) acc[oi][ti] += wv[oi] * xv[ti];
    }
    #pragma unroll
    for (int oi = 0; oi < 4; oi++)
        #pragma unroll
        for (int ti = 0; ti < 8; ti++)
            g_Y[((size_t)b * 64 + o0 + oi) * NTOK + y * 64 + ti * 8 + tg] = acc[oi][ti];
}

// ---------------------------------------------------------------------------
// Stage 3b: bilinear 2x (align_corners=False) + LeakyReLU + residual.
// One CTA per (channel, batch); Y plane staged in smem; coalesced I/O.
// ---------------------------------------------------------------------------
__global__ __launch_bounds__(256) void final_kernel(
    const float* __restrict__ rgb, float* __restrict__ out) {
    int c = blockIdx.x, b = blockIdx.y;
    __shared__ float Ys[64][65];
    int tid = threadIdx.x;

    const float* Yb = g_Y + ((size_t)b * 64 + c) * NTOK;
    for (int i = tid; i < 4096; i += 256) Ys[i >> 6][i & 63] = Yb[i];
    __syncthreads();

    const float* Rb = rgb + ((size_t)b * 64 + c) * 16384;
    float* Ob = out + ((size_t)b * 64 + c) * 16384;

    #pragma unroll 4
    for (int rep = 0; rep < 16; rep++) {
        int cell = tid + rep * 256;
        int h = cell >> 6, w = cell & 63;
        int hm = max(h - 1, 0), hp = min(h + 1, 63);
        int wm = max(w - 1, 0), wp = min(w + 1, 63);
        float a0 = Ys[hm][wm], a1 = Ys[hm][w], a2 = Ys[hm][wp];
        float b0 = Ys[h][wm],  b1 = Ys[h][w],  b2 = Ys[h][wp];
        float c0 = Ys[hp][wm], c1 = Ys[hp][w], c2 = Ys[hp][wp];
        float u0 = 0.25f * a0 + 0.75f * b0;
        float u1 = 0.25f * a1 + 0.75f * b1;
        float u2 = 0.25f * a2 + 0.75f * b2;
        float d0 = 0.75f * b0 + 0.25f * c0;
        float d1 = 0.75f * b1 + 0.25f * c1;
        float d2 = 0.75f * b2 + 0.25f * c2;
        float o00 = 0.25f * u0 + 0.75f * u1, o01 = 0.75f * u1 + 0.25f * u2;
        float o10 = 0.25f * d0 + 0.75f * d1, o11 = 0.75f * d1 + 0.25f * d2;
        o00 = (o00 >= 0.f) ? o00 : 0.2f * o00;
        o01 = (o01 >= 0.f) ? o01 : 0.2f * o01;
        o10 = (o10 >= 0.f) ? o10 : 0.2f * o10;
        o11 = (o11 >= 0.f) ? o11 : 0.2f * o11;
        float2 r0 = *(const float2*)(Rb + (2 * h) * 128 + 2 * w);
        float2 r1 = *(const float2*)(Rb + (2 * h + 1) * 128 + 2 * w);
        *(float2*)(Ob + (2 * h) * 128 + 2 * w) = make_float2(r0.x + o00, r0.y + o01);
        *(float2*)(Ob + (2 * h + 1) * 128 + 2 * w) = make_float2(r1.x + o10, r1.y + o11);
    }
}

// ---------------------------------------------------------------------------
extern "C" void kernel_launch(void* const* d_in, const int* in_sizes, int n_in,
                              void* d_out, int out_size) {
    const float* rgb   = (const float*)d_in[0];
    const float* freq  = (const float*)d_in[1];
    const float* w_q   = (const float*)d_in[2];
    const float* b_q   = (const float*)d_in[3];
    const float* w_k   = (const float*)d_in[4];
    const float* b_k   = (const float*)d_in[5];
    const float* w_v   = (const float*)d_in[6];
    const float* b_v   = (const float*)d_in[7];
    const float* w_o   = (const float*)d_in[8];
    const float* b_o   = (const float*)d_in[9];
    const float* gamma = (const float*)d_in[10];
    const float* beta  = (const float*)d_in[11];
    const float* mean  = (const float*)d_in[12];
    const float* var   = (const float*)d_in[13];
    float* out = (float*)d_out;

    qkv_kernel<<<dim3(64, 8, 2), 128>>>(rgb, freq, w_q, b_q, w_k, b_k, w_v, b_v);
    attn_kernel<<<dim3(32, 8), 256>>>();
    convo_kernel<<<dim3(64, 8), 128>>>(w_o, b_o, gamma, beta, mean, var);
    final_kernel<<<dim3(64, 8), 256>>>(rgb, out);
}

// round 6
// speedup vs baseline: 1.3019x; 1.0954x over previous
#include <cuda_runtime.h>
#include <cuda_fp16.h>
#include <cstdint>

// ---------------------------------------------------------------------------
// CMA block: pool2x2 -> QKV 1x1 conv -> softmax attention (N=4096, d=64) ->
// O 1x1 conv + BN (folded, done at low res) -> bilinear 2x -> lrelu -> +rgb
// Attention: legacy mma.sync with f16 accumulators (2x rate vs f32 accum;
// tcgen05 rejected by the bench toolchain: PTX target is base sm_103).
// ---------------------------------------------------------------------------

#define BB 8
#define NTOK 4096   // 64*64 tokens per batch
#define DD 64
// scale * log2(e) folded into Q so softmax numerator = exp2(q'.k)
#define QSCALE 0.18033688011112042f

// scratch (device globals: no allocation allowed)
__device__ __align__(16) __half g_Q[BB * NTOK * DD];   // [b][n][c]
__device__ __align__(16) __half g_K[BB * NTOK * DD];   // [b][n][c]
__device__ __align__(16) __half g_V[BB * DD * NTOK];   // [b][c][n]
__device__ __align__(16) float g_Z[BB * NTOK * DD];    // attn out [b][n][c]
__device__ __align__(16) float g_Y[BB * DD * NTOK];    // o-proj   [b][c][n]

__device__ __forceinline__ unsigned packh(float lo, float hi) {
    __half2 h = __floats2half2_rn(lo, hi);
    return *(unsigned*)&h;
}
// exp2 on both halves of an f16x2 register
__device__ __forceinline__ unsigned hex2(unsigned x) {
    unsigned r; asm("ex2.approx.f16x2 %0, %1;" : "=r"(r) : "r"(x)); return r;
}
__device__ __forceinline__ __half2 uh2(unsigned x) { return *(__half2*)&x; }

// f16-accumulator MMA: D(f16x2 x2) = A(f16 m16k16) * B(f16 k16n8) + D
__device__ __forceinline__ void mma_h(unsigned (&d)[2], const unsigned (&a)[4],
                                      unsigned b0, unsigned b1) {
    asm volatile(
        "mma.sync.aligned.m16n8k16.row.col.f16.f16.f16.f16 "
        "{%0,%1}, {%2,%3,%4,%5}, {%6,%7}, {%0,%1};\n"
        : "+r"(d[0]), "+r"(d[1])
        : "r"(a[0]), "r"(a[1]), "r"(a[2]), "r"(a[3]), "r"(b0), "r"(b1));
}
__device__ __forceinline__ void ldsm4(unsigned& r0, unsigned& r1, unsigned& r2,
                                      unsigned& r3, uint32_t addr) {
    asm volatile("ldmatrix.sync.aligned.m8n8.x4.shared.b16 {%0,%1,%2,%3}, [%4];"
                 : "=r"(r0), "=r"(r1), "=r"(r2), "=r"(r3) : "r"(addr));
}
__device__ __forceinline__ void cp16(uint32_t s, const void* g) {
    asm volatile("cp.async.cg.shared.global [%0], [%1], 16;" :: "r"(s), "l"(g));
}

// ---------------------------------------------------------------------------
// Stage 1: pool 2x2 + QKV projection. grid (64 ds-rows, B, 2 modes).
// mode 0: Q from rgb; mode 1: K then V from freq (freq read ONCE).
// ---------------------------------------------------------------------------
__device__ __forceinline__ void proj_compute(
    const float (*xs)[64], const float (*Ws)[65], const float* bias,
    int tid, float (&acc)[4][8]) {
    int og = tid >> 3, tg = tid & 7;
    int o0 = og * 4;
    #pragma unroll
    for (int oi = 0; oi < 4; oi++) {
        float bv = bias[o0 + oi];
        #pragma unroll
        for (int ti = 0; ti < 8; ti++) acc[oi][ti] = bv;
    }
    for (int c = 0; c < 64; c++) {
        float wv[4], xv[8];
        #pragma unroll
        for (int oi = 0; oi < 4; oi++) wv[oi] = Ws[c][o0 + oi];
        #pragma unroll
        for (int ti = 0; ti < 8; ti++) xv[ti] = xs[c][ti * 8 + tg];
        #pragma unroll
        for (int oi = 0; oi < 4; oi++)
            #pragma unroll
            for (int ti = 0; ti < 8; ti++) acc[oi][ti] += wv[oi] * xv[ti];
    }
}

__global__ __launch_bounds__(128) void qkv_kernel(
    const float* __restrict__ rgb, const float* __restrict__ freq,
    const float* __restrict__ w_q, const float* __restrict__ b_q,
    const float* __restrict__ w_k, const float* __restrict__ b_k,
    const float* __restrict__ w_v, const float* __restrict__ b_v) {
    int y = blockIdx.x, b = blockIdx.y, mode = blockIdx.z;
    __shared__ float xs[64][64];   // pooled input [c][t]
    __shared__ float Ws[64][65];   // weights transposed [c][o]
    int tid = threadIdx.x;
    int tg = tid & 7, o0 = (tid >> 3) * 4;

    const float* src = (mode == 0) ? rgb : freq;
    const float* base = src + (((size_t)b * 64) * 128 + 2 * y) * 128;
    for (int idx = tid; idx < 4096; idx += 128) {
        int c = idx >> 6, t = idx & 63;
        const float* p = base + (size_t)c * 128 * 128 + 2 * t;
        float2 a0 = *(const float2*)p;
        float2 a1 = *(const float2*)(p + 128);
        xs[c][t] = 0.25f * (a0.x + a0.y + a1.x + a1.y);
    }
    const float* w0 = (mode == 0) ? w_q : w_k;
    for (int idx = tid; idx < 4096; idx += 128) {
        int o = idx >> 6, c = idx & 63;
        Ws[c][o] = w0[idx];
    }
    __syncthreads();

    float acc[4][8];
    proj_compute(xs, Ws, (mode == 0) ? b_q : b_k, tid, acc);

    if (mode == 0) {   // Q: [b][n][c], pre-scaled by QSCALE
        #pragma unroll
        for (int ti = 0; ti < 8; ti++) {
            int t = ti * 8 + tg;
            size_t rowoff = ((size_t)b * NTOK + y * 64 + t) * 64 + o0;
            #pragma unroll
            for (int oi = 0; oi < 4; oi += 2)
                *(unsigned*)&g_Q[rowoff + oi] =
                    packh(acc[oi][ti] * QSCALE, acc[oi + 1][ti] * QSCALE);
        }
        return;
    }
    // K: [b][n][c]
    #pragma unroll
    for (int ti = 0; ti < 8; ti++) {
        int t = ti * 8 + tg;
        size_t rowoff = ((size_t)b * NTOK + y * 64 + t) * 64 + o0;
        #pragma unroll
        for (int oi = 0; oi < 4; oi += 2)
            *(unsigned*)&g_K[rowoff + oi] = packh(acc[oi][ti], acc[oi + 1][ti]);
    }
    __syncthreads();   // all Ws reads done before reload
    for (int idx = tid; idx < 4096; idx += 128) {
        int o = idx >> 6, c = idx & 63;
        Ws[c][o] = w_v[idx];
    }
    __syncthreads();
    proj_compute(xs, Ws, b_v, tid, acc);
    // V: [b][c][n]
    #pragma unroll
    for (int oi = 0; oi < 4; oi++)
        #pragma unroll
        for (int ti = 0; ti < 8; ti++) {
            int t = ti * 8 + tg;
            g_V[((size_t)b * 64 + o0 + oi) * NTOK + y * 64 + t] =
                __float2half_rn(acc[oi][ti]);
        }
}

// ---------------------------------------------------------------------------
// Stage 2: fused attention, f16-accum mma.sync.
// BM=128 queries per CTA, BN=64 keys/iter, 8 warps, 2 CTA/SM.
// No max-subtraction (logits tiny): p = exp2(q'.k), z = sum(p*V)/sum(p).
// S arrives in f16x2; ex2.approx.f16x2 output IS the next A-fragment.
// ---------------------------------------------------------------------------
__global__ __launch_bounds__(256, 2) void attn_kernel() {
    int b = blockIdx.y;
    int qbase = blockIdx.x * 128;
    // [stage][K/V][row][72]: row stride 144B (conflict-free for ldmatrix)
    __shared__ __align__(16) __half KVs[2][2][64][72];

    int tid = threadIdx.x, lane = tid & 31, warp = tid >> 5;
    int grp = lane >> 2, tig = lane & 3;

    const __half* Kp = g_K + (size_t)b * NTOK * 64;
    const __half* Vp = g_V + (size_t)b * 64 * NTOK;

    // A-fragments for Q loaded directly from gmem (once)
    unsigned qa[4][4];
    {
        const __half* Qp = g_Q + ((size_t)b * NTOK + qbase + warp * 16 + grp) * 64;
        #pragma unroll
        for (int ks = 0; ks < 4; ks++) {
            qa[ks][0] = *(const unsigned*)(Qp + ks * 16 + tig * 2);
            qa[ks][1] = *(const unsigned*)(Qp + 8 * 64 + ks * 16 + tig * 2);
            qa[ks][2] = *(const unsigned*)(Qp + ks * 16 + 8 + tig * 2);
            qa[ks][3] = *(const unsigned*)(Qp + 8 * 64 + ks * 16 + 8 + tig * 2);
        }
    }

    uint32_t sb = (uint32_t)__cvta_generic_to_shared(&KVs[0][0][0][0]);
    const int STG = 2 * 64 * 144;   // stage stride bytes
    const int KVD = 64 * 144;       // K->V stride bytes
    uint32_t lmoff = (uint32_t)((lane & 7) * 144 + (lane >> 3) * 16);

    int r0i = tid, r1i = tid + 256;
    int row0 = r0i >> 3, ch0 = r0i & 7, row1 = r1i >> 3, ch1 = r1i & 7;

    auto issue = [&](int kt, int st) {
        uint32_t kd = sb + st * STG;
        uint32_t vd = kd + KVD;
        cp16(kd + row0 * 144 + ch0 * 16, Kp + (kt * 64 + row0) * 64 + ch0 * 8);
        cp16(kd + row1 * 144 + ch1 * 16, Kp + (kt * 64 + row1) * 64 + ch1 * 8);
        cp16(vd + row0 * 144 + ch0 * 16, Vp + (size_t)row0 * NTOK + kt * 64 + ch0 * 8);
        cp16(vd + row1 * 144 + ch1 * 16, Vp + (size_t)row1 * NTOK + kt * 64 + ch1 * 8);
        asm volatile("cp.async.commit_group;" ::: "memory");
    };

    unsigned oacc[8][2];
    #pragma unroll
    for (int dt = 0; dt < 8; dt++) { oacc[dt][0] = 0u; oacc[dt][1] = 0u; }
    float den0 = 0.f, den1 = 0.f;

    issue(0, 0);

    for (int kt = 0; kt < 64; kt++) {
        int st = kt & 1;
        asm volatile("cp.async.wait_group 0;" ::: "memory");
        __syncthreads();
        if (kt + 1 < 64) issue(kt + 1, st ^ 1);

        uint32_t Kb = sb + st * STG + lmoff;
        uint32_t Vb = Kb + KVD;

        unsigned pa[4][4];
        #pragma unroll
        for (int j = 0; j < 4; j++) {
            unsigned s0[2] = {0u, 0u}, s1[2] = {0u, 0u};
            unsigned kb0[8], kb1[8];
            ldsm4(kb0[0], kb0[1], kb0[2], kb0[3], Kb + (2 * j) * 1152);
            ldsm4(kb0[4], kb0[5], kb0[6], kb0[7], Kb + (2 * j) * 1152 + 64);
            ldsm4(kb1[0], kb1[1], kb1[2], kb1[3], Kb + (2 * j + 1) * 1152);
            ldsm4(kb1[4], kb1[5], kb1[6], kb1[7], Kb + (2 * j + 1) * 1152 + 64);
            #pragma unroll
            for (int ks = 0; ks < 4; ks++) {
                mma_h(s0, qa[ks], kb0[2 * ks], kb0[2 * ks + 1]);
                mma_h(s1, qa[ks], kb1[2 * ks], kb1[2 * ks + 1]);
            }
            // p = exp2(s); f16x2 output doubles as A-fragment for P@V
            pa[j][0] = hex2(s0[0]);   // rows grp,   cols 2tig..+1, tile 2j
            pa[j][1] = hex2(s0[1]);   // rows grp+8
            pa[j][2] = hex2(s1[0]);   // tile 2j+1
            pa[j][3] = hex2(s1[1]);
        }
        // denominator: within-iter f16 trees (rows grp / grp+8 kept apart),
        // cross-iter accumulation in f32.
        {
            __half2 a0 = __hadd2(__hadd2(uh2(pa[0][0]), uh2(pa[0][2])),
                                 __hadd2(uh2(pa[1][0]), uh2(pa[1][2])));
            __half2 a1 = __hadd2(__hadd2(uh2(pa[2][0]), uh2(pa[2][2])),
                                 __hadd2(uh2(pa[3][0]), uh2(pa[3][2])));
            float2 f0 = __half22float2(__hadd2(a0, a1));
            den0 += f0.x + f0.y;
            __half2 b0h = __hadd2(__hadd2(uh2(pa[0][1]), uh2(pa[0][3])),
                                  __hadd2(uh2(pa[1][1]), uh2(pa[1][3])));
            __half2 b1h = __hadd2(__hadd2(uh2(pa[2][1]), uh2(pa[2][3])),
                                  __hadd2(uh2(pa[3][1]), uh2(pa[3][3])));
            float2 f1 = __half22float2(__hadd2(b0h, b1h));
            den1 += f1.x + f1.y;
        }
        // O += P @ V
        #pragma unroll
        for (int dt = 0; dt < 8; dt++) {
            unsigned vb[8];
            ldsm4(vb[0], vb[1], vb[2], vb[3], Vb + dt * 1152);
            ldsm4(vb[4], vb[5], vb[6], vb[7], Vb + dt * 1152 + 64);
            #pragma unroll
            for (int j = 0; j < 4; j++)
                mma_h(oacc[dt], pa[j], vb[2 * j], vb[2 * j + 1]);
        }
    }

    den0 += __shfl_xor_sync(0xffffffffu, den0, 1);
    den0 += __shfl_xor_sync(0xffffffffu, den0, 2);
    den1 += __shfl_xor_sync(0xffffffffu, den1, 1);
    den1 += __shfl_xor_sync(0xffffffffu, den1, 2);
    float i0 = 1.f / den0, i1 = 1.f / den1;

    int r0 = qbase + warp * 16 + grp, r1 = r0 + 8;
    #pragma unroll
    for (int dt = 0; dt < 8; dt++) {
        int c = dt * 8 + tig * 2;
        float2 o0 = __half22float2(uh2(oacc[dt][0]));
        float2 o1 = __half22float2(uh2(oacc[dt][1]));
        *(float2*)&g_Z[((size_t)b * NTOK + r0) * 64 + c] =
            make_float2(o0.x * i0, o0.y * i0);
        *(float2*)&g_Z[((size_t)b * NTOK + r1) * 64 + c] =
            make_float2(o1.x * i1, o1.y * i1);
    }
}

// ---------------------------------------------------------------------------
// Stage 3a: O-projection + folded BN at 64x64 resolution. grid (64 ds-rows, B).
// ---------------------------------------------------------------------------
__global__ __launch_bounds__(128) void convo_kernel(
    const float* __restrict__ w_o, const float* __restrict__ b_o,
    const float* __restrict__ gamma, const float* __restrict__ beta,
    const float* __restrict__ mean, const float* __restrict__ var) {
    int y = blockIdx.x, b = blockIdx.y;
    __shared__ float zs[64][65];
    __shared__ float Wsm[64][65];
    __shared__ float invs[64], bsm[64];
    int tid = threadIdx.x;

    if (tid < 64) {
        float inv = gamma[tid] * rsqrtf(var[tid] + 1e-5f);
        invs[tid] = inv;
        bsm[tid] = (b_o[tid] - mean[tid]) * inv + beta[tid];
    }
    __syncthreads();
    for (int idx = tid; idx < 4096; idx += 128) {
        int o = idx >> 6, c = idx & 63;
        Wsm[c][o] = w_o[idx] * invs[o];
    }
    for (int idx = tid; idx < 4096; idx += 128) {
        int t = idx >> 6, c = idx & 63;
        zs[t][c] = g_Z[((size_t)b * NTOK + y * 64 + t) * 64 + c];
    }
    __syncthreads();

    int og = tid >> 3, tg = tid & 7;
    int o0 = og * 4;
    float acc[4][8];
    #pragma unroll
    for (int oi = 0; oi < 4; oi++) {
        float bv = bsm[o0 + oi];
        #pragma unroll
        for (int ti = 0; ti < 8; ti++) acc[oi][ti] = bv;
    }
    for (int c = 0; c < 64; c++) {
        float wv[4], xv[8];
        #pragma unroll
        for (int oi = 0; oi < 4; oi++) wv[oi] = Wsm[c][o0 + oi];
        #pragma unroll
        for (int ti = 0; ti < 8; ti++) xv[ti] = zs[ti * 8 + tg][c];
        #pragma unroll
        for (int oi = 0; oi < 4; oi++)
            #pragma unroll
            for (int ti = 0; ti < 8; ti++) acc[oi][ti] += wv[oi] * xv[ti];
    }
    #pragma unroll
    for (int oi = 0; oi < 4; oi++)
        #pragma unroll
        for (int ti = 0; ti < 8; ti++)
            g_Y[((size_t)b * 64 + o0 + oi) * NTOK + y * 64 + ti * 8 + tg] = acc[oi][ti];
}

// ---------------------------------------------------------------------------
// Stage 3b: bilinear 2x (align_corners=False) + LeakyReLU + residual.
// One CTA per (channel, batch); Y plane staged in smem; coalesced I/O.
// ---------------------------------------------------------------------------
__global__ __launch_bounds__(256) void final_kernel(
    const float* __restrict__ rgb, float* __restrict__ out) {
    int c = blockIdx.x, b = blockIdx.y;
    __shared__ float Ys[64][65];
    int tid = threadIdx.x;

    const float* Yb = g_Y + ((size_t)b * 64 + c) * NTOK;
    for (int i = tid; i < 4096; i += 256) Ys[i >> 6][i & 63] = Yb[i];
    __syncthreads();

    const float* Rb = rgb + ((size_t)b * 64 + c) * 16384;
    float* Ob = out + ((size_t)b * 64 + c) * 16384;

    #pragma unroll 4
    for (int rep = 0; rep < 16; rep++) {
        int cell = tid + rep * 256;
        int h = cell >> 6, w = cell & 63;
        int hm = max(h - 1, 0), hp = min(h + 1, 63);
        int wm = max(w - 1, 0), wp = min(w + 1, 63);
        float a0 = Ys[hm][wm], a1 = Ys[hm][w], a2 = Ys[hm][wp];
        float b0 = Ys[h][wm],  b1 = Ys[h][w],  b2 = Ys[h][wp];
        float c0 = Ys[hp][wm], c1 = Ys[hp][w], c2 = Ys[hp][wp];
        float u0 = 0.25f * a0 + 0.75f * b0;
        float u1 = 0.25f * a1 + 0.75f * b1;
        float u2 = 0.25f * a2 + 0.75f * b2;
        float d0 = 0.75f * b0 + 0.25f * c0;
        float d1 = 0.75f * b1 + 0.25f * c1;
        float d2 = 0.75f * b2 + 0.25f * c2;
        float o00 = 0.25f * u0 + 0.75f * u1, o01 = 0.75f * u1 + 0.25f * u2;
        float o10 = 0.25f * d0 + 0.75f * d1, o11 = 0.75f * d1 + 0.25f * d2;
        o00 = (o00 >= 0.f) ? o00 : 0.2f * o00;
        o01 = (o01 >= 0.f) ? o01 : 0.2f * o01;
        o10 = (o10 >= 0.f) ? o10 : 0.2f * o10;
        o11 = (o11 >= 0.f) ? o11 : 0.2f * o11;
        float2 r0 = *(const float2*)(Rb + (2 * h) * 128 + 2 * w);
        float2 r1 = *(const float2*)(Rb + (2 * h + 1) * 128 + 2 * w);
        *(float2*)(Ob + (2 * h) * 128 + 2 * w) = make_float2(r0.x + o00, r0.y + o01);
        *(float2*)(Ob + (2 * h + 1) * 128 + 2 * w) = make_float2(r1.x + o10, r1.y + o11);
    }
}

// ---------------------------------------------------------------------------
extern "C" void kernel_launch(void* const* d_in, const int* in_sizes, int n_in,
                              void* d_out, int out_size) {
    const float* rgb   = (const float*)d_in[0];
    const float* freq  = (const float*)d_in[1];
    const float* w_q   = (const float*)d_in[2];
    const float* b_q   = (const float*)d_in[3];
    const float* w_k   = (const float*)d_in[4];
    const float* b_k   = (const float*)d_in[5];
    const float* w_v   = (const float*)d_in[6];
    const float* b_v   = (const float*)d_in[7];
    const float* w_o   = (const float*)d_in[8];
    const float* b_o   = (const float*)d_in[9];
    const float* gamma = (const float*)d_in[10];
    const float* beta  = (const float*)d_in[11];
    const float* mean  = (const float*)d_in[12];
    const float* var   = (const float*)d_in[13];
    float* out = (float*)d_out;

    qkv_kernel<<<dim3(64, 8, 2), 128>>>(rgb, freq, w_q, b_q, w_k, b_k, w_v, b_v);
    attn_kernel<<<dim3(32, 8), 256>>>();
    convo_kernel<<<dim3(64, 8), 128>>>(w_o, b_o, gamma, beta, mean, var);
    final_kernel<<<dim3(64, 8), 256>>>(rgb, out);
}